// round 1
// baseline (speedup 1.0000x reference)
#include <cuda_runtime.h>

#define NG 128
#define FEAT 16
#define WIDTH 64
#define NUM_POS 3
#define IN_MLP 25          // FEAT + NUM_POS*3
#define MAX_PTS 262144

// Scratch: interpolated features per point (16 MB). __device__ global per harness rules.
__device__ float g_feat[MAX_PTS * FEAT];

__device__ __forceinline__ void cubic_w(float t, float w[4]) {
    float t2 = t * t, t3 = t2 * t;
    w[0] = 0.5f * (-t3 + 2.0f * t2 - t);
    w[1] = 0.5f * (3.0f * t3 - 5.0f * t2 + 2.0f);
    w[2] = 0.5f * (-3.0f * t3 + 4.0f * t2 + t);
    w[3] = 0.5f * (t3 - t2);
}

// Kernel 1: tricubic gather. 16 lanes per point: lane = (c, fg),
// c = z-tap (0..3), fg = feature float4 group (0..3).
// Per (a,b) tap the 16 lanes read one contiguous 256B block -> coalesced.
__global__ __launch_bounds__(256) void gather_kernel(
    const float* __restrict__ x,
    const float* __restrict__ grid,
    int npts)
{
    int gtid = blockIdx.x * 256 + threadIdx.x;
    int pt = gtid >> 4;
    if (pt >= npts) return;
    int sub = gtid & 15;
    int c  = sub >> 2;
    int fg = sub & 3;

    float ux = x[3 * pt + 0] * 127.0f;
    float uy = x[3 * pt + 1] * 127.0f;
    float uz = x[3 * pt + 2] * 127.0f;
    float fx = floorf(ux), fy = floorf(uy), fz = floorf(uz);
    float tx = ux - fx, ty = uy - fy, tz = uz - fz;
    int ix0 = (int)fx, iy0 = (int)fy, iz0 = (int)fz;

    float wx[4], wy[4], wz[4];
    cubic_w(tx, wx);
    cubic_w(ty, wy);
    cubic_w(tz, wz);
    float wzc = wz[c];
    int zi = min(max(iz0 + c - 1, 0), NG - 1);

    float4 acc = make_float4(0.f, 0.f, 0.f, 0.f);
    #pragma unroll
    for (int a = 0; a < 4; a++) {
        int xi = min(max(ix0 + a - 1, 0), NG - 1);
        const float* gx = grid + (size_t)xi * (NG * NG * FEAT);
        float wxa = wx[a];
        #pragma unroll
        for (int b = 0; b < 4; b++) {
            int yi = min(max(iy0 + b - 1, 0), NG - 1);
            float w = wxa * wy[b] * wzc;
            const float4* gp =
                reinterpret_cast<const float4*>(gx + (yi * NG + zi) * FEAT) + fg;
            float4 v = __ldg(gp);
            acc.x += w * v.x;
            acc.y += w * v.y;
            acc.z += w * v.z;
            acc.w += w * v.w;
        }
    }

    // Reduce over the 4 z-taps: lanes differing in bits 2 and 3 of lane id.
    const unsigned m = 0xFFFFFFFFu;
    acc.x += __shfl_xor_sync(m, acc.x, 4);
    acc.y += __shfl_xor_sync(m, acc.y, 4);
    acc.z += __shfl_xor_sync(m, acc.z, 4);
    acc.w += __shfl_xor_sync(m, acc.w, 4);
    acc.x += __shfl_xor_sync(m, acc.x, 8);
    acc.y += __shfl_xor_sync(m, acc.y, 8);
    acc.z += __shfl_xor_sync(m, acc.z, 8);
    acc.w += __shfl_xor_sync(m, acc.w, 8);

    if (c == 0) {
        reinterpret_cast<float4*>(g_feat)[pt * 4 + fg] = acc;
    }
}

// Kernel 2: positional encoding + MLP (25 -> 64 swish -> 1), 1 thread / point.
__global__ __launch_bounds__(256) void mlp_kernel(
    const float* __restrict__ x,
    const float* __restrict__ w1,
    const float* __restrict__ b1,
    const float* __restrict__ w2,
    const float* __restrict__ b2,
    float* __restrict__ out,
    int npts)
{
    __shared__ float s_w1[WIDTH][28];   // 25 padded to 28 (16B-aligned rows)
    __shared__ float s_b1[WIDTH];
    __shared__ float s_w2[WIDTH];
    __shared__ float s_b2;

    for (int i = threadIdx.x; i < WIDTH * IN_MLP; i += 256)
        s_w1[i / IN_MLP][i % IN_MLP] = w1[i];
    if (threadIdx.x < WIDTH) {
        s_b1[threadIdx.x] = b1[threadIdx.x];
        s_w2[threadIdx.x] = w2[threadIdx.x];
    }
    if (threadIdx.x == 0) s_b2 = b2[0];
    __syncthreads();

    int n = blockIdx.x * 256 + threadIdx.x;
    if (n >= npts) return;

    float h[IN_MLP];
    const float4* fb = reinterpret_cast<const float4*>(g_feat) + n * 4;
    float4 f0 = fb[0], f1 = fb[1], f2 = fb[2], f3 = fb[3];
    h[0] = f0.x;  h[1] = f0.y;  h[2] = f0.z;  h[3] = f0.w;
    h[4] = f1.x;  h[5] = f1.y;  h[6] = f1.z;  h[7] = f1.w;
    h[8] = f2.x;  h[9] = f2.y;  h[10] = f2.z; h[11] = f2.w;
    h[12] = f3.x; h[13] = f3.y; h[14] = f3.z; h[15] = f3.w;

    float t[3];
    #pragma unroll
    for (int d = 0; d < 3; d++) {
        float u = x[3 * n + d] * 127.0f;
        t[d] = u - floorf(u);
    }
    const float TWO_PI = 6.283185307179586f;
    #pragma unroll
    for (int k = 0; k < NUM_POS; k++) {
        #pragma unroll
        for (int d = 0; d < 3; d++) {
            h[FEAT + 3 * k + d] = __sinf(TWO_PI * (float)(k + 1) * t[d]);
        }
    }

    float acc = s_b2;
    #pragma unroll 8
    for (int j = 0; j < WIDTH; j++) {
        float s = s_b1[j];
        const float* row = s_w1[j];
        #pragma unroll
        for (int i = 0; i < IN_MLP; i++) s += row[i] * h[i];
        // swish(s) = s * sigmoid(s)
        float sig = __fdividef(1.0f, 1.0f + __expf(-s));
        acc += s_w2[j] * (s * sig);
    }
    out[n] = acc;
}

extern "C" void kernel_launch(void* const* d_in, const int* in_sizes, int n_in,
                              void* d_out, int out_size) {
    const float* x    = (const float*)d_in[0];
    const float* grid = (const float*)d_in[1];
    const float* w1   = (const float*)d_in[2];
    const float* b1   = (const float*)d_in[3];
    const float* w2   = (const float*)d_in[4];
    const float* b2   = (const float*)d_in[5];
    float* out = (float*)d_out;

    int npts = in_sizes[0] / 3;
    if (npts > MAX_PTS) npts = MAX_PTS;

    int gather_threads = npts * 16;
    int gblocks = (gather_threads + 255) / 256;
    gather_kernel<<<gblocks, 256>>>(x, grid, npts);

    int mblocks = (npts + 255) / 256;
    mlp_kernel<<<mblocks, 256>>>(x, w1, b1, w2, b2, out, npts);
}